// round 6
// baseline (speedup 1.0000x reference)
#include <cuda_runtime.h>
#include <math.h>

// Problem constants
#define Bsz 4
#define Tn  1024
#define Dm  1024
#define Hn  16
#define HSz 64
#define Ln  4
#define FFn 4096
#define Vn  32000
#define EPSf 1e-5f
#define BT  (Bsz*Tn)   // 4096
#define SCALE 0.125f   // HS^-0.5

// ---------------- scratch (device globals; allocation is forbidden) -------
__device__ float g_x[BT*Dm];          // residual stream        16 MB
__device__ float g_h[BT*Dm];          // layernorm output       16 MB
__device__ float g_qkv[BT*3*Dm];      // fused QKV              48 MB
__device__ float g_o[BT*Dm];          // attention output       16 MB
__device__ float g_ffn[BT*FFn];       // FFN activation         64 MB
__device__ float g_wt[Dm*3*Dm];       // transposed QKV weights 12 MB
__device__ float g_logits[BT*Vn];     // logits                524 MB
__device__ float g_nll[BT];

// ---------------- embedding ----------------------------------------------
__global__ void embed_kernel(const int* __restrict__ idx,
                             const float* __restrict__ tok,
                             const float* __restrict__ pos) {
    int gid = blockIdx.x * 256 + threadIdx.x;      // BT*Dm threads
    int bt = gid >> 10;
    int d  = gid & 1023;
    int t  = bt & (Tn - 1);
    g_x[gid] = tok[(size_t)idx[bt] * Dm + d] + pos[t * Dm + d];
}

// ---------------- layernorm (row = 1024, block = 256) ---------------------
__global__ void ln_kernel(const float* __restrict__ x,
                          const float* __restrict__ g,
                          const float* __restrict__ b,
                          float* __restrict__ out) {
    int row = blockIdx.x, tid = threadIdx.x;
    const float* xr = x + (size_t)row * Dm;
    float v[4]; float s = 0.f;
    #pragma unroll
    for (int i = 0; i < 4; i++) { v[i] = xr[tid + i*256]; s += v[i]; }
    __shared__ float red[256];
    red[tid] = s; __syncthreads();
    for (int st = 128; st > 0; st >>= 1) { if (tid < st) red[tid] += red[tid+st]; __syncthreads(); }
    float m = red[0] * (1.0f / Dm);
    __syncthreads();
    float sq = 0.f;
    #pragma unroll
    for (int i = 0; i < 4; i++) { float d = v[i] - m; sq += d * d; }
    red[tid] = sq; __syncthreads();
    for (int st = 128; st > 0; st >>= 1) { if (tid < st) red[tid] += red[tid+st]; __syncthreads(); }
    float inv = rsqrtf(red[0] * (1.0f / Dm) + EPSf);
    #pragma unroll
    for (int i = 0; i < 4; i++) {
        int d = tid + i*256;
        out[(size_t)row * Dm + d] = (v[i] - m) * inv * g[d] + b[d];
    }
}

// ---------------- QKV weight transpose: [H,D,HS] -> [D, 3*D] --------------
__global__ void wtrans_kernel(const float* __restrict__ Wq,
                              const float* __restrict__ Wk,
                              const float* __restrict__ Wv) {
    int gid = blockIdx.x * 256 + threadIdx.x;   // Dm*Dm threads
    int d = gid >> 10;
    int c = gid & 1023;        // c = h*HS + s
    int h = c >> 6, s = c & 63;
    int src = (h * Dm + d) * HSz + s;
    g_wt[(size_t)d * 3*Dm + c]          = Wq[src];
    g_wt[(size_t)d * 3*Dm + Dm + c]     = Wk[src];
    g_wt[(size_t)d * 3*Dm + 2*Dm + c]   = Wv[src];
}

// ---------------- SGEMM: C = A[M,K] @ B[K,N] (+bias)(+C)(relu) ------------
// 128x128 tile, BK=8, 256 threads, 8x8 microtile. M%128==0, N%128==0, K%8==0.
#define FLAG_RELU  1
#define FLAG_RESID 2
__global__ void __launch_bounds__(256) sgemm_kernel(
        const float* __restrict__ A, const float* __restrict__ B,
        const float* __restrict__ bias, float* __restrict__ C,
        int M, int N, int K, int flags) {
    __shared__ float As[8][128];
    __shared__ float Bs[8][128];
    int tid  = threadIdx.x;
    int brow = blockIdx.y * 128;
    int bcol = blockIdx.x * 128;
    int aRow = tid >> 1;            // 0..127
    int aCol = (tid & 1) * 4;       // 0 or 4
    int bRow = tid >> 5;            // 0..7
    int bCol = (tid & 31) * 4;      // 0..124
    int tr = (tid >> 4) * 8;        // 0..120 step 8
    int tc = (tid & 15) * 8;

    float acc[8][8];
    #pragma unroll
    for (int i = 0; i < 8; i++)
        #pragma unroll
        for (int j = 0; j < 8; j++) acc[i][j] = 0.f;

    const float* Aptr = A + (size_t)brow * K;
    const float* Bptr = B + bcol;

    for (int k0 = 0; k0 < K; k0 += 8) {
        float4 av = *(const float4*)(Aptr + (size_t)aRow * K + k0 + aCol);
        As[aCol+0][aRow] = av.x; As[aCol+1][aRow] = av.y;
        As[aCol+2][aRow] = av.z; As[aCol+3][aRow] = av.w;
        float4 bv = *(const float4*)(Bptr + (size_t)(k0 + bRow) * N + bCol);
        *(float4*)&Bs[bRow][bCol] = bv;
        __syncthreads();
        #pragma unroll
        for (int kk = 0; kk < 8; kk++) {
            float a[8], bb[8];
            #pragma unroll
            for (int i = 0; i < 8; i++) a[i]  = As[kk][tr + i];
            #pragma unroll
            for (int j = 0; j < 8; j++) bb[j] = Bs[kk][tc + j];
            #pragma unroll
            for (int i = 0; i < 8; i++)
                #pragma unroll
                for (int j = 0; j < 8; j++) acc[i][j] += a[i] * bb[j];
        }
        __syncthreads();
    }

    #pragma unroll
    for (int i = 0; i < 8; i++) {
        size_t row = (size_t)(brow + tr + i);
        float* crow = C + row * N + bcol + tc;
        #pragma unroll
        for (int j = 0; j < 8; j++) {
            float v = acc[i][j];
            if (bias) v += bias[bcol + tc + j];
            if (flags & FLAG_RESID) v += crow[j];
            if (flags & FLAG_RELU)  v = fmaxf(v, 0.f);
            crow[j] = v;
        }
    }
}

// ---------------- attention scores: S = Q @ K^T * scale -------------------
// grid (T/64 [kt], T/64 [qt], B*H); 64x64 tile; skips upper-triangular tiles.
__global__ void __launch_bounds__(256) scores_kernel(float* __restrict__ attn) {
    int kt = blockIdx.x, qt = blockIdx.y;
    if (kt > qt) return;
    int bh = blockIdx.z;
    int b = bh >> 4, h = bh & 15;
    __shared__ float Qs[64][68];
    __shared__ float Ks[64][68];
    int tid = threadIdx.x;
    int lr = tid >> 4;           // 0..15
    int lc = (tid & 15) * 4;     // 0..60
    #pragma unroll
    for (int r = 0; r < 4; r++) {
        int row = r * 16 + lr;
        const float* qp = g_qkv + (size_t)(b*Tn + qt*64 + row) * (3*Dm) + h*HSz + lc;
        float4 qv = *(const float4*)qp;
        Qs[row][lc] = qv.x; Qs[row][lc+1] = qv.y; Qs[row][lc+2] = qv.z; Qs[row][lc+3] = qv.w;
        const float* kp = g_qkv + (size_t)(b*Tn + kt*64 + row) * (3*Dm) + Dm + h*HSz + lc;
        float4 kv = *(const float4*)kp;
        Ks[row][lc] = kv.x; Ks[row][lc+1] = kv.y; Ks[row][lc+2] = kv.z; Ks[row][lc+3] = kv.w;
    }
    __syncthreads();
    int tr = lr * 4, tc = lc;   // 4x4 microtile
    float acc[4][4] = {};
    #pragma unroll
    for (int kk = 0; kk < 64; kk++) {
        float a[4], bb[4];
        #pragma unroll
        for (int i = 0; i < 4; i++) a[i]  = Qs[tr + i][kk];
        #pragma unroll
        for (int j = 0; j < 4; j++) bb[j] = Ks[tc + j][kk];
        #pragma unroll
        for (int i = 0; i < 4; i++)
            #pragma unroll
            for (int j = 0; j < 4; j++) acc[i][j] += a[i] * bb[j];
    }
    float* outp = attn + (size_t)bh * Tn * Tn;
    #pragma unroll
    for (int i = 0; i < 4; i++)
        #pragma unroll
        for (int j = 0; j < 4; j++)
            outp[(size_t)(qt*64 + tr + i) * Tn + kt*64 + tc + j] = acc[i][j] * SCALE;
}

// ---------------- causal softmax in-place over d_out attn rows ------------
// grid (T [t], B*H); block 256
__global__ void __launch_bounds__(256) softmax_kernel(float* __restrict__ attn) {
    int t = blockIdx.x, bh = blockIdx.y, tid = threadIdx.x;
    float* row = attn + (size_t)bh * Tn * Tn + (size_t)t * Tn;
    int valid = t + 1;
    float v[4];
    float m = -1e30f;
    #pragma unroll
    for (int i = 0; i < 4; i++) {
        int j = tid + i*256;
        v[i] = row[j];
        if (j < valid) m = fmaxf(m, v[i]);
    }
    __shared__ float red[256];
    red[tid] = m; __syncthreads();
    for (int st = 128; st > 0; st >>= 1) { if (tid < st) red[tid] = fmaxf(red[tid], red[tid+st]); __syncthreads(); }
    m = red[0]; __syncthreads();
    float s = 0.f;
    #pragma unroll
    for (int i = 0; i < 4; i++) {
        int j = tid + i*256;
        float e = (j < valid) ? expf(v[i] - m) : 0.f;
        v[i] = e; s += e;
    }
    red[tid] = s; __syncthreads();
    for (int st = 128; st > 0; st >>= 1) { if (tid < st) red[tid] += red[tid+st]; __syncthreads(); }
    float inv = 1.0f / red[0];
    #pragma unroll
    for (int i = 0; i < 4; i++) row[tid + i*256] = v[i] * inv;
}

// ---------------- O = P @ V (causal k-loop) -------------------------------
// grid (T/64 [qt], B*H). NOTE: attn base is d_out+1 (4 mod 16 bytes), so the
// probability tile must be read with scalar (32-bit) loads, never float4.
__global__ void __launch_bounds__(256) av_kernel(const float* __restrict__ attn,
                                                 float* __restrict__ O) {
    int qt = blockIdx.x, bh = blockIdx.y;
    int b = bh >> 4, h = bh & 15;
    __shared__ float Ps[64][68];
    __shared__ float Vs[64][68];
    int tid = threadIdx.x;
    int lr = tid >> 4;
    int lc = (tid & 15) * 4;
    int tr = lr * 4, tc = lc;
    float acc[4][4] = {};
    const float* abase = attn + (size_t)bh * Tn * Tn;
    for (int kt = 0; kt <= qt; kt++) {
        #pragma unroll
        for (int r = 0; r < 4; r++) {
            int row = r * 16 + lr;
            const float* pp = abase + (size_t)(qt*64 + row) * Tn + kt*64 + lc;
            Ps[row][lc]   = pp[0];
            Ps[row][lc+1] = pp[1];
            Ps[row][lc+2] = pp[2];
            Ps[row][lc+3] = pp[3];
            const float* vp = g_qkv + (size_t)(b*Tn + kt*64 + row) * (3*Dm) + 2*Dm + h*HSz + lc;
            float4 vv = *(const float4*)vp;
            Vs[row][lc] = vv.x; Vs[row][lc+1] = vv.y; Vs[row][lc+2] = vv.z; Vs[row][lc+3] = vv.w;
        }
        __syncthreads();
        #pragma unroll
        for (int kk = 0; kk < 64; kk++) {
            float a[4], bb[4];
            #pragma unroll
            for (int i = 0; i < 4; i++) a[i]  = Ps[tr + i][kk];
            #pragma unroll
            for (int j = 0; j < 4; j++) bb[j] = Vs[kk][tc + j];
            #pragma unroll
            for (int i = 0; i < 4; i++)
                #pragma unroll
                for (int j = 0; j < 4; j++) acc[i][j] += a[i] * bb[j];
        }
        __syncthreads();
    }
    #pragma unroll
    for (int i = 0; i < 4; i++)
        #pragma unroll
        for (int j = 0; j < 4; j++)
            O[(size_t)(b*Tn + qt*64 + tr + i) * Dm + h*HSz + tc + j] = acc[i][j];
}

// ---------------- per-row NLL over 32000-way logits -----------------------
__global__ void __launch_bounds__(512) nll_kernel(const int* __restrict__ targets) {
    int row = blockIdx.x, tid = threadIdx.x;
    const float* lr = g_logits + (size_t)row * Vn;
    float m = -1e30f;
    for (int j = tid; j < Vn; j += 512) m = fmaxf(m, lr[j]);
    __shared__ float red[512];
    red[tid] = m; __syncthreads();
    for (int st = 256; st > 0; st >>= 1) { if (tid < st) red[tid] = fmaxf(red[tid], red[tid+st]); __syncthreads(); }
    m = red[0]; __syncthreads();
    float s = 0.f;
    for (int j = tid; j < Vn; j += 512) s += expf(lr[j] - m);
    red[tid] = s; __syncthreads();
    for (int st = 256; st > 0; st >>= 1) { if (tid < st) red[tid] += red[tid+st]; __syncthreads(); }
    if (tid == 0) {
        int tg = targets[row];
        g_nll[row] = -(lr[tg] - m - logf(red[0]));
    }
}

__global__ void __launch_bounds__(256) loss_reduce_kernel(float* __restrict__ out) {
    int tid = threadIdx.x;
    float s = 0.f;
    for (int i = tid; i < BT; i += 256) s += g_nll[i];
    __shared__ float red[256];
    red[tid] = s; __syncthreads();
    for (int st = 128; st > 0; st >>= 1) { if (tid < st) red[tid] += red[tid+st]; __syncthreads(); }
    if (tid == 0) out[0] = red[0] / (float)BT;
}

// ---------------- launch ---------------------------------------------------
extern "C" void kernel_launch(void* const* d_in, const int* in_sizes, int n_in,
                              void* d_out, int out_size) {
    const int*   idx     = (const int*)  d_in[0];
    const int*   targets = (const int*)  d_in[1];
    const float* tok     = (const float*)d_in[2];
    const float* pos     = (const float*)d_in[3];
    const float* ln1_g   = (const float*)d_in[4];
    const float* ln1_b   = (const float*)d_in[5];
    const float* Wq      = (const float*)d_in[6];
    const float* Wk      = (const float*)d_in[7];
    const float* Wv      = (const float*)d_in[8];
    const float* Wp      = (const float*)d_in[9];
    const float* bp      = (const float*)d_in[10];
    const float* ln2_g   = (const float*)d_in[11];
    const float* ln2_b   = (const float*)d_in[12];
    const float* W1      = (const float*)d_in[13];
    const float* b1      = (const float*)d_in[14];
    const float* W2      = (const float*)d_in[15];
    const float* b2      = (const float*)d_in[16];
    const float* lnf_g   = (const float*)d_in[17];
    const float* lnf_b   = (const float*)d_in[18];
    const float* Wlm     = (const float*)d_in[19];
    const float* blm     = (const float*)d_in[20];

    float* out = (float*)d_out;
    float* attn_all = out + 1;   // (loss, attn) flattened

    float *px, *ph, *pqkv, *po, *pffn, *pwt, *plogits;
    cudaGetSymbolAddress((void**)&px,      g_x);
    cudaGetSymbolAddress((void**)&ph,      g_h);
    cudaGetSymbolAddress((void**)&pqkv,    g_qkv);
    cudaGetSymbolAddress((void**)&po,      g_o);
    cudaGetSymbolAddress((void**)&pffn,    g_ffn);
    cudaGetSymbolAddress((void**)&pwt,     g_wt);
    cudaGetSymbolAddress((void**)&plogits, g_logits);

    embed_kernel<<<(BT*Dm)/256, 256>>>(idx, tok, pos);

    for (int l = 0; l < Ln; l++) {
        float* attn_l = attn_all + (size_t)l * Bsz * Hn * Tn * Tn;
        size_t woff = (size_t)l * Hn * Dm * HSz;

        ln_kernel<<<BT, 256>>>(px, ln1_g + l*Dm, ln1_b + l*Dm, ph);
        wtrans_kernel<<<(Dm*Dm)/256, 256>>>(Wq + woff, Wk + woff, Wv + woff);
        sgemm_kernel<<<dim3(3*Dm/128, BT/128), 256>>>(ph, pwt, nullptr, pqkv,
                                                      BT, 3*Dm, Dm, 0);
        scores_kernel<<<dim3(Tn/64, Tn/64, Bsz*Hn), 256>>>(attn_l);
        softmax_kernel<<<dim3(Tn, Bsz*Hn), 256>>>(attn_l);
        av_kernel<<<dim3(Tn/64, Bsz*Hn), 256>>>(attn_l, po);
        sgemm_kernel<<<dim3(Dm/128, BT/128), 256>>>(po, Wp + (size_t)l*Dm*Dm,
                                                    bp + l*Dm, px,
                                                    BT, Dm, Dm, FLAG_RESID);
        ln_kernel<<<BT, 256>>>(px, ln2_g + l*Dm, ln2_b + l*Dm, ph);
        sgemm_kernel<<<dim3(FFn/128, BT/128), 256>>>(ph, W1 + (size_t)l*Dm*FFn,
                                                     b1 + l*FFn, pffn,
                                                     BT, FFn, Dm, FLAG_RELU);
        sgemm_kernel<<<dim3(Dm/128, BT/128), 256>>>(pffn, W2 + (size_t)l*FFn*Dm,
                                                    b2 + l*Dm, px,
                                                    BT, Dm, FFn, FLAG_RESID);
    }

    ln_kernel<<<BT, 256>>>(px, lnf_g, lnf_b, ph);
    sgemm_kernel<<<dim3(Vn/128, BT/128), 256>>>(ph, Wlm, blm, plogits,
                                                BT, Vn, Dm, 0);
    nll_kernel<<<BT, 512>>>(targets);
    loss_reduce_kernel<<<1, 256>>>(out);
}